// round 16
// baseline (speedup 1.0000x reference)
#include <cuda_runtime.h>
#include <cstdint>

#define BSZ  32
#define SEQL 64
#define HID  256

// scratch (no cudaMalloc allowed)
__device__ float g_context[BSZ * HID];

// ---------- helpers ----------
__device__ __forceinline__ uint32_t s2u(const void* p) {
    uint32_t a;
    asm("{ .reg .u64 t; cvta.to.shared.u64 t, %1; cvt.u32.u64 %0, t; }" : "=r"(a) : "l"(p));
    return a;
}
__device__ __forceinline__ void ffma2(unsigned long long& d, unsigned long long a, unsigned long long b) {
    asm("fma.rn.f32x2 %0, %1, %2, %3;" : "=l"(d) : "l"(a), "l"(b), "l"(d));
}
__device__ __forceinline__ unsigned long long pk2(float a, float b) {
    unsigned long long r;
    asm("mov.b64 %0, {%1, %2};" : "=l"(r) : "f"(a), "f"(b));
    return r;
}
__device__ __forceinline__ float2 upk2(unsigned long long v) {
    float2 f;
    asm("mov.b64 {%0, %1}, %2;" : "=f"(f.x), "=f"(f.y) : "l"(v));
    return f;
}
__device__ __forceinline__ float tanh_mufu(float x) {
    float r;
    asm("tanh.approx.f32 %0, %1;" : "=f"(r) : "f"(x));
    return r;
}
__device__ __forceinline__ float sig_mufu(float x) {
    return fmaf(tanh_mufu(0.5f * x), 0.5f, 0.5f);
}
__device__ __forceinline__ void mbar_init(uint32_t addr, uint32_t cnt) {
    asm volatile("mbarrier.init.shared.b64 [%0], %1;" :: "r"(addr), "r"(cnt) : "memory");
}
__device__ __forceinline__ void mbar_arrive_expect(uint32_t addr, uint32_t tx) {
    asm volatile("mbarrier.arrive.expect_tx.shared.b64 _, [%0], %1;" :: "r"(addr), "r"(tx) : "memory");
}
__device__ __forceinline__ void mbar_wait(uint32_t addr, uint32_t parity) {
    asm volatile(
        "{\n\t"
        ".reg .pred P;\n\t"
        "WAIT_%=: \n\t"
        "mbarrier.try_wait.parity.acquire.cta.shared::cta.b64 P, [%0], %1, 0x989680;\n\t"
        "@!P bra WAIT_%=;\n\t"
        "}"
        :: "r"(addr), "r"(parity) : "memory");
}
__device__ __forceinline__ void st_async_f32(uint32_t laddr, uint32_t lbar, float v, int rank) {
    uint32_t ra, rb;
    asm("mapa.shared::cluster.u32 %0, %1, %2;" : "=r"(ra) : "r"(laddr), "r"(rank));
    asm("mapa.shared::cluster.u32 %0, %1, %2;" : "=r"(rb) : "r"(lbar), "r"(rank));
    asm volatile("st.async.shared::cluster.mbarrier::complete_tx::bytes.f32 [%0], %1, [%2];"
                 :: "r"(ra), "f"(v), "r"(rb) : "memory");
}

// ============================================================================
// K1: context[b][h] = sum_s softmax_s(x[b]@Wa_x)[s,h] * x[b,s,h]
// grid 128 = (b:32) x (hchunk:4), 256 threads   (unchanged — verified)
// ============================================================================
__global__ void __launch_bounds__(256) k_context(const float* __restrict__ x,
                                                 const float* __restrict__ Wa) {
    __shared__ __align__(16) float xt[64][65];
    __shared__ __align__(16) float wt_sc[64][64];

    const int b   = blockIdx.x >> 2;
    const int hc  = blockIdx.x & 3;
    const int tid = threadIdx.x;
    const int h4  = tid & 15;
    const int s4  = tid >> 4;
    const float* xb = x + b * SEQL * HID;

    float acc[4][4];
#pragma unroll
    for (int i = 0; i < 4; i++)
#pragma unroll
        for (int j = 0; j < 4; j++) acc[i][j] = 0.0f;

    for (int kt = 0; kt < 4; ++kt) {
#pragma unroll
        for (int it = 0; it < 16; ++it) {
            int i = it * 256 + tid;
            int s = i >> 6, kk = i & 63;
            xt[kk][s] = xb[s * HID + kt * 64 + kk];
        }
#pragma unroll
        for (int it = 0; it < 16; ++it) {
            int i = it * 256 + tid;
            int kk = i >> 6, hl = i & 63;
            wt_sc[kk][hl] = Wa[(kt * 64 + kk) * HID + hc * 64 + hl];
        }
        __syncthreads();
#pragma unroll 4
        for (int kk = 0; kk < 64; ++kk) {
            float a0 = xt[kk][s4 * 4 + 0];
            float a1 = xt[kk][s4 * 4 + 1];
            float a2 = xt[kk][s4 * 4 + 2];
            float a3 = xt[kk][s4 * 4 + 3];
            float4 wv = *reinterpret_cast<const float4*>(&wt_sc[kk][h4 * 4]);
            acc[0][0] += a0 * wv.x; acc[0][1] += a0 * wv.y; acc[0][2] += a0 * wv.z; acc[0][3] += a0 * wv.w;
            acc[1][0] += a1 * wv.x; acc[1][1] += a1 * wv.y; acc[1][2] += a1 * wv.z; acc[1][3] += a1 * wv.w;
            acc[2][0] += a2 * wv.x; acc[2][1] += a2 * wv.y; acc[2][2] += a2 * wv.z; acc[2][3] += a2 * wv.w;
            acc[3][0] += a3 * wv.x; acc[3][1] += a3 * wv.y; acc[3][2] += a3 * wv.z; acc[3][3] += a3 * wv.w;
        }
        __syncthreads();
    }

#pragma unroll
    for (int i = 0; i < 4; ++i) {
        *reinterpret_cast<float4*>(&wt_sc[s4 * 4 + i][h4 * 4]) =
            make_float4(acc[i][0], acc[i][1], acc[i][2], acc[i][3]);
    }
    __syncthreads();

    if (tid < 64) {
        const int h = tid;
        float m = -3.4e38f;
#pragma unroll 8
        for (int s = 0; s < 64; ++s) m = fmaxf(m, wt_sc[s][h]);
        float Z = 0.0f, C = 0.0f;
#pragma unroll 8
        for (int s = 0; s < 64; ++s) {
            float e = __expf(wt_sc[s][h] - m);
            Z += e;
            C += e * xb[s * HID + hc * 64 + h];
        }
        g_context[b * HID + hc * 64 + h] = C / Z;
    }
}

// ============================================================================
// K3: LSTM recurrence, 2-DEEP BATCH PIPELINE on the FULL CHIP.
// 16 clusters x 8 CTAs; cluster g owns batches 2g, 2g+1. CTA rank r owns
// h in [r*32, r*32+32). thread = (hl: tid>>4, cp: (tid>>3)&1, kq: tid&7).
// Each period t advances both batches one step via 2 sequential phases;
// batch b's DSMEM exchange latency hides behind the other batch's phase.
// Per phase: wait mbar[t&1][b] -> sync -> matvec(b) -> shfl reduces ->
// MUFU pointwise (all lanes hold all gates; ct[2] replicated in all lanes)
// -> cp==0 lanes scatter h(b,hl) to rank kq (st.async; own rank via STS).
// ============================================================================
#define BLKF 36   // floats per kq block (32 data + 4 pad) -> conflict-free LDS
#define NB   2    // batches per cluster

__global__ void __cluster_dims__(8, 1, 1) __launch_bounds__(512, 1)
k_recur(const float* __restrict__ Wi, const float* __restrict__ Wh,
        const float* __restrict__ bias, const float* __restrict__ Wf,
        const float* __restrict__ bf, float* __restrict__ out) {
    __shared__ __align__(16) float htbuf[2][NB][8][BLKF];  // [buf][batch][srcrank][36]
    __shared__ __align__(16) float ctx_s[NB][256];
    __shared__ __align__(16) float gb_sA[NB][2][32];       // [batch][cp][hl]
    __shared__ __align__(16) float gb_sB[NB][2][32];
    __shared__ float red_s[16];
    __shared__ __align__(8) unsigned long long mbar[2][NB];  // [buf][batch]

    const int tid = threadIdx.x;
    uint32_t rnk;
    asm("mov.u32 %0, %%cluster_ctarank;" : "=r"(rnk));
    const int r     = (int)rnk;
    const int g     = blockIdx.x >> 3;      // cluster index 0..15
    const int cbase = g * NB;               // first batch of this cluster
    const int hl = tid >> 4;          // 0..31
    const int cp = (tid >> 3) & 1;    // 0..1
    const int kq = tid & 7;           // 0..7
    const int colA = (2 * cp) * 256 + r * 32 + hl;   // gate 2cp
    const int colB = colA + 256;                     // gate 2cp+1

    const int wrp  = tid >> 5;
    const int lane = tid & 31;

    const uint32_t htb   = s2u(&htbuf[0][0][0][0]);
    const uint32_t mbarb = s2u(&mbar[0][0]);

    // ---- init: zero both buffers, load contexts, arm all mbarriers ----
    for (int i = tid; i < 2 * NB * 8 * BLKF; i += 512) ((float*)htbuf)[i] = 0.0f;
    { int b2 = tid >> 8, k = tid & 255;
      ctx_s[b2][k] = g_context[(cbase + b2) * HID + k]; }
    if (tid < 2 * NB) {
        uint32_t ba = mbarb + (uint32_t)(tid * 8);
        mbar_init(ba, 1);
        mbar_arrive_expect(ba, 896);   // 224 remote 4B sends per batch-step
    }
    __syncthreads();

    // ---- gbase = bias + ctx @ Wi for NB batches ----
    {
        float gbA[NB] = {0.f, 0.f}, gbB[NB] = {0.f, 0.f};
#pragma unroll 4
        for (int k = kq * 32; k < kq * 32 + 32; ++k) {
            float w0 = __ldg(&Wi[k * 1024 + colA]);
            float w1 = __ldg(&Wi[k * 1024 + colB]);
#pragma unroll
            for (int b = 0; b < NB; ++b) {
                float c = ctx_s[b][k];
                gbA[b] += c * w0;
                gbB[b] += c * w1;
            }
        }
#pragma unroll
        for (int off = 1; off < 8; off <<= 1) {
#pragma unroll
            for (int b = 0; b < NB; ++b) {
                gbA[b] += __shfl_xor_sync(0xffffffffu, gbA[b], off);
                gbB[b] += __shfl_xor_sync(0xffffffffu, gbB[b], off);
            }
        }
        float bA = __ldg(&bias[colA]);
        float bB = __ldg(&bias[colB]);
        if (kq == 0) {
#pragma unroll
            for (int b = 0; b < NB; ++b) {
                gb_sA[b][cp][hl] = gbA[b] + bA;
                gb_sB[b][cp][hl] = gbB[b] + bB;
            }
        }
    }

    // ---- Wh slice -> registers (32 k x 2 cols as f32x2 pairs) ----
    unsigned long long wA[16], wB[16];
#pragma unroll
    for (int p = 0; p < 16; ++p) {
        int k = kq * 32 + 2 * p;
        wA[p] = pk2(__ldg(&Wh[k * 1024 + colA]), __ldg(&Wh[(k + 1) * 1024 + colA]));
        wB[p] = pk2(__ldg(&Wh[k * 1024 + colB]), __ldg(&Wh[(k + 1) * 1024 + colB]));
    }
    __syncthreads();
    // one-time: all CTAs' mbarriers armed + zeroed ht visible before any st.async
    asm volatile("barrier.cluster.arrive.aligned;" ::: "memory");
    asm volatile("barrier.cluster.wait.aligned;" ::: "memory");

    float ct[NB] = {0.f, 0.f};

    // ---- 64 periods x NB phases ----
    for (int t = 0; t < 64; ++t) {
        const uint32_t rbuf = (uint32_t)(t & 1);
        const uint32_t wbuf = (uint32_t)((t + 1) & 1);
        const uint32_t wpar = (uint32_t)(((t - 1) >> 1) & 1);
#pragma unroll
        for (int b = 0; b < NB; ++b) {
            if (t > 0) {
                uint32_t ba = mbarb + (rbuf * NB + (uint32_t)b) * 8u;
                if (wrp == 0) {
                    mbar_wait(ba, wpar);
                    if (lane == 0) mbar_arrive_expect(ba, 896);  // re-arm t+2
                }
                __syncthreads();
            }

            // matvec for batch b over this lane's k-block (conflict-free)
            unsigned long long accA = 0ull, accB = 0ull;
            const uint32_t a = htb +
                (uint32_t)((((rbuf * NB + (uint32_t)b) * 8 + (uint32_t)kq) * BLKF) * 4);
#pragma unroll
            for (int q = 0; q < 8; ++q) {
                unsigned long long hA, hB;
                asm volatile("ld.shared.v2.u64 {%0, %1}, [%2];"
                             : "=l"(hA), "=l"(hB) : "r"(a + (uint32_t)(q * 16)));
                ffma2(accA, wA[2 * q],     hA);
                ffma2(accA, wA[2 * q + 1], hB);
                ffma2(accB, wB[2 * q],     hA);
                ffma2(accB, wB[2 * q + 1], hB);
            }
            float2 fA = upk2(accA), fB = upk2(accB);
            float pA = fA.x + fA.y;
            float pB = fB.x + fB.y;

            // all-reduce over the 8 kq lanes
#pragma unroll
            for (int off = 1; off < 8; off <<= 1) {
                pA += __shfl_xor_sync(0xffffffffu, pA, off);
                pB += __shfl_xor_sync(0xffffffffu, pB, off);
            }
            pA += gb_sA[b][cp][hl];
            pB += gb_sB[b][cp][hl];

            // exchange with opposite-cp lane -> every lane has all 4 gates
            float qA = __shfl_xor_sync(0xffffffffu, pA, 8);
            float qB = __shfl_xor_sync(0xffffffffu, pB, 8);
            float gi = cp ? qA : pA;
            float gf = cp ? qB : pB;
            float gg = cp ? pA : qA;
            float go = cp ? pB : qB;

            float c  = sig_mufu(gf) * ct[b] + sig_mufu(gi) * tanh_mufu(gg);
            ct[b] = c;
            float hv = sig_mufu(go) * tanh_mufu(c);

            // scatter: cp==0 lanes (32 hl x 8 kq) send h(b,hl) to rank kq
            if (cp == 0) {
                uint32_t laddr = htb +
                    (uint32_t)(((((wbuf * NB + (uint32_t)b) * 8 + (uint32_t)r) * BLKF) + (uint32_t)hl) * 4);
                if (kq == r) {
                    asm volatile("st.shared.f32 [%0], %1;" :: "r"(laddr), "f"(hv) : "memory");
                } else {
                    st_async_f32(laddr, mbarb + (wbuf * NB + (uint32_t)b) * 8u, hv, kq);
                }
            }
        }
    }

    // ---- final waits: ht(64) of each batch lands in buf 0, parity 1 ----
    if (wrp == 0) {
#pragma unroll
        for (int b = 0; b < NB; ++b)
            mbar_wait(mbarb + (uint32_t)(b * 8), 1);
    }
    __syncthreads();

    // ---- epilogue: out[cbase+b] = ht_b @ Wf + bf (rank 0 only) ----
    if (r == 0) {
        int b2 = tid >> 8, k = tid & 255;
        float v = htbuf[0][b2][k >> 5][k & 31] * Wf[k];
#pragma unroll
        for (int off = 16; off > 0; off >>= 1) v += __shfl_xor_sync(0xffffffffu, v, off);
        if ((tid & 31) == 0) red_s[tid >> 5] = v;
        __syncthreads();
        if (tid == 0) {
            float o = bf[0];
#pragma unroll
            for (int w = 0; w < 8; ++w) o += red_s[w];
            out[cbase] = o;
        }
        if (tid == 256) {
            float o = bf[0];
#pragma unroll
            for (int w = 8; w < 16; ++w) o += red_s[w];
            out[cbase + 1] = o;
        }
    }
    // keep the cluster alive until everyone is done with peers' smem
    asm volatile("barrier.cluster.arrive.aligned;" ::: "memory");
    asm volatile("barrier.cluster.wait.aligned;" ::: "memory");
}

// ============================================================================
extern "C" void kernel_launch(void* const* d_in, const int* in_sizes, int n_in,
                              void* d_out, int out_size) {
    (void)in_sizes; (void)n_in; (void)out_size;
    const float* x    = (const float*)d_in[0];
    const float* Wa   = (const float*)d_in[1];
    // d_in[2] = ba : constant across seq, cancels inside softmax — unused
    const float* Wi   = (const float*)d_in[3];
    const float* Wh   = (const float*)d_in[4];
    const float* bias = (const float*)d_in[5];
    const float* Wf   = (const float*)d_in[6];
    const float* bf   = (const float*)d_in[7];
    float* out = (float*)d_out;

    k_context<<<128, 256>>>(x, Wa);
    k_recur<<<128, 512>>>(Wi, Wh, bias, Wf, bf, out);
}

// round 17
// speedup vs baseline: 1.2348x; 1.2348x over previous
#include <cuda_runtime.h>
#include <cstdint>

#define BSZ  32
#define SEQL 64
#define HID  256

// scratch (no cudaMalloc allowed)
__device__ float g_context[BSZ * HID];

// ---------- helpers ----------
__device__ __forceinline__ uint32_t s2u(const void* p) {
    uint32_t a;
    asm("{ .reg .u64 t; cvta.to.shared.u64 t, %1; cvt.u32.u64 %0, t; }" : "=r"(a) : "l"(p));
    return a;
}
__device__ __forceinline__ void ffma2(unsigned long long& d, unsigned long long a, unsigned long long b) {
    asm("fma.rn.f32x2 %0, %1, %2, %3;" : "=l"(d) : "l"(a), "l"(b), "l"(d));
}
__device__ __forceinline__ unsigned long long pk2(float a, float b) {
    unsigned long long r;
    asm("mov.b64 %0, {%1, %2};" : "=l"(r) : "f"(a), "f"(b));
    return r;
}
__device__ __forceinline__ float2 upk2(unsigned long long v) {
    float2 f;
    asm("mov.b64 {%0, %1}, %2;" : "=f"(f.x), "=f"(f.y) : "l"(v));
    return f;
}
__device__ __forceinline__ float tanh_mufu(float x) {
    float r;
    asm("tanh.approx.f32 %0, %1;" : "=f"(r) : "f"(x));
    return r;
}
__device__ __forceinline__ float sig_mufu(float x) {
    return fmaf(tanh_mufu(0.5f * x), 0.5f, 0.5f);
}
__device__ __forceinline__ void mbar_init(uint32_t addr, uint32_t cnt) {
    asm volatile("mbarrier.init.shared.b64 [%0], %1;" :: "r"(addr), "r"(cnt) : "memory");
}
__device__ __forceinline__ void mbar_arrive_expect(uint32_t addr, uint32_t tx) {
    asm volatile("mbarrier.arrive.expect_tx.shared.b64 _, [%0], %1;" :: "r"(addr), "r"(tx) : "memory");
}
__device__ __forceinline__ void mbar_wait(uint32_t addr, uint32_t parity) {
    asm volatile(
        "{\n\t"
        ".reg .pred P;\n\t"
        "WAIT_%=: \n\t"
        "mbarrier.try_wait.parity.acquire.cta.shared::cta.b64 P, [%0], %1, 0x989680;\n\t"
        "@!P bra WAIT_%=;\n\t"
        "}"
        :: "r"(addr), "r"(parity) : "memory");
}
__device__ __forceinline__ void st_async_f32(uint32_t laddr, uint32_t lbar, float v, int rank) {
    uint32_t ra, rb;
    asm("mapa.shared::cluster.u32 %0, %1, %2;" : "=r"(ra) : "r"(laddr), "r"(rank));
    asm("mapa.shared::cluster.u32 %0, %1, %2;" : "=r"(rb) : "r"(lbar), "r"(rank));
    asm volatile("st.async.shared::cluster.mbarrier::complete_tx::bytes.f32 [%0], %1, [%2];"
                 :: "r"(ra), "f"(v), "r"(rb) : "memory");
}

// ============================================================================
// K1: context[b][h] = sum_s softmax_s(x[b]@Wa_x)[s,h] * x[b,s,h]
// grid 128 = (b:32) x (hchunk:4), 256 threads   (unchanged — verified)
// ============================================================================
__global__ void __launch_bounds__(256) k_context(const float* __restrict__ x,
                                                 const float* __restrict__ Wa) {
    __shared__ __align__(16) float xt[64][65];
    __shared__ __align__(16) float wt_sc[64][64];

    const int b   = blockIdx.x >> 2;
    const int hc  = blockIdx.x & 3;
    const int tid = threadIdx.x;
    const int h4  = tid & 15;
    const int s4  = tid >> 4;
    const float* xb = x + b * SEQL * HID;

    float acc[4][4];
#pragma unroll
    for (int i = 0; i < 4; i++)
#pragma unroll
        for (int j = 0; j < 4; j++) acc[i][j] = 0.0f;

    for (int kt = 0; kt < 4; ++kt) {
#pragma unroll
        for (int it = 0; it < 16; ++it) {
            int i = it * 256 + tid;
            int s = i >> 6, kk = i & 63;
            xt[kk][s] = xb[s * HID + kt * 64 + kk];
        }
#pragma unroll
        for (int it = 0; it < 16; ++it) {
            int i = it * 256 + tid;
            int kk = i >> 6, hl = i & 63;
            wt_sc[kk][hl] = Wa[(kt * 64 + kk) * HID + hc * 64 + hl];
        }
        __syncthreads();
#pragma unroll 4
        for (int kk = 0; kk < 64; ++kk) {
            float a0 = xt[kk][s4 * 4 + 0];
            float a1 = xt[kk][s4 * 4 + 1];
            float a2 = xt[kk][s4 * 4 + 2];
            float a3 = xt[kk][s4 * 4 + 3];
            float4 wv = *reinterpret_cast<const float4*>(&wt_sc[kk][h4 * 4]);
            acc[0][0] += a0 * wv.x; acc[0][1] += a0 * wv.y; acc[0][2] += a0 * wv.z; acc[0][3] += a0 * wv.w;
            acc[1][0] += a1 * wv.x; acc[1][1] += a1 * wv.y; acc[1][2] += a1 * wv.z; acc[1][3] += a1 * wv.w;
            acc[2][0] += a2 * wv.x; acc[2][1] += a2 * wv.y; acc[2][2] += a2 * wv.z; acc[2][3] += a2 * wv.w;
            acc[3][0] += a3 * wv.x; acc[3][1] += a3 * wv.y; acc[3][2] += a3 * wv.z; acc[3][3] += a3 * wv.w;
        }
        __syncthreads();
    }

#pragma unroll
    for (int i = 0; i < 4; ++i) {
        *reinterpret_cast<float4*>(&wt_sc[s4 * 4 + i][h4 * 4]) =
            make_float4(acc[i][0], acc[i][1], acc[i][2], acc[i][3]);
    }
    __syncthreads();

    if (tid < 64) {
        const int h = tid;
        float m = -3.4e38f;
#pragma unroll 8
        for (int s = 0; s < 64; ++s) m = fmaxf(m, wt_sc[s][h]);
        float Z = 0.0f, C = 0.0f;
#pragma unroll 8
        for (int s = 0; s < 64; ++s) {
            float e = __expf(wt_sc[s][h] - m);
            Z += e;
            C += e * xb[s * HID + hc * 64 + h];
        }
        g_context[b * HID + hc * 64 + h] = C / Z;
    }
}

// ============================================================================
// K3: LSTM recurrence, 4-DEEP BATCH PIPELINE, SYNC-FREE PHASES.
// 8 clusters x 8 CTAs; cluster g owns batches 4g..4g+3. CTA rank r owns
// h in [r*32, r*32+32). thread = (hl: tid>>4, cp: (tid>>3)&1, kq: tid&7).
// Per phase (NO __syncthreads anywhere in the loop):
//   every warp acquire-waits mbar[t&1][b] (all ht deliveries, incl. the
//   self slice, are st.async-tracked so the barrier orders everything);
//   (wrp0,lane0) re-arms for t+2; matvec(b); kq-butterfly reduce; +gbase
//   (register-resident); cp-exchange shfl; all-lane MUFU pointwise
//   (ct[b] replicated in every lane); cp==0 lanes st.async h(b,hl) to
//   rank kq (OWN rank also via st.async -> tracked). expect_tx = 1024B.
// ============================================================================
#define BLKF 36   // floats per kq block (32 data + 4 pad) -> conflict-free LDS
#define NB   4    // batches per cluster

__global__ void __cluster_dims__(8, 1, 1) __launch_bounds__(512, 1)
k_recur(const float* __restrict__ Wi, const float* __restrict__ Wh,
        const float* __restrict__ bias, const float* __restrict__ Wf,
        const float* __restrict__ bf, float* __restrict__ out) {
    __shared__ __align__(16) float htbuf[2][NB][8][BLKF];  // [buf][batch][srcrank][36]
    __shared__ __align__(16) float ctx_s[NB][256];
    __shared__ float red_s[16];
    __shared__ __align__(8) unsigned long long mbar[2][NB];  // [buf][batch]

    const int tid = threadIdx.x;
    uint32_t rnk;
    asm("mov.u32 %0, %%cluster_ctarank;" : "=r"(rnk));
    const int r     = (int)rnk;
    const int g     = blockIdx.x >> 3;      // cluster index 0..7
    const int cbase = g * NB;               // first batch of this cluster
    const int hl = tid >> 4;          // 0..31
    const int cp = (tid >> 3) & 1;    // 0..1
    const int kq = tid & 7;           // 0..7
    const int colA = (2 * cp) * 256 + r * 32 + hl;   // gate 2cp
    const int colB = colA + 256;                     // gate 2cp+1

    const int wrp  = tid >> 5;
    const int lane = tid & 31;

    const uint32_t htb   = s2u(&htbuf[0][0][0][0]);
    const uint32_t mbarb = s2u(&mbar[0][0]);

    // ---- init: zero both buffers, load contexts, arm all mbarriers ----
    for (int i = tid; i < 2 * NB * 8 * BLKF; i += 512) ((float*)htbuf)[i] = 0.0f;
    for (int i = tid; i < NB * 256; i += 512)
        ((float*)ctx_s)[i] = g_context[(cbase + (i >> 8)) * HID + (i & 255)];
    if (tid < 2 * NB) {
        uint32_t ba = mbarb + (uint32_t)(tid * 8);
        mbar_init(ba, 1);
        mbar_arrive_expect(ba, 1024);   // 256 x 4B per batch-step (incl. self)
    }
    __syncthreads();

    // ---- gbase = bias + ctx @ Wi for NB batches (kept in REGISTERS) ----
    float gbA[NB] = {0.f, 0.f, 0.f, 0.f}, gbB[NB] = {0.f, 0.f, 0.f, 0.f};
#pragma unroll 4
    for (int k = kq * 32; k < kq * 32 + 32; ++k) {
        float w0 = __ldg(&Wi[k * 1024 + colA]);
        float w1 = __ldg(&Wi[k * 1024 + colB]);
#pragma unroll
        for (int b = 0; b < NB; ++b) {
            float c = ctx_s[b][k];
            gbA[b] += c * w0;
            gbB[b] += c * w1;
        }
    }
#pragma unroll
    for (int off = 1; off < 8; off <<= 1) {
#pragma unroll
        for (int b = 0; b < NB; ++b) {
            gbA[b] += __shfl_xor_sync(0xffffffffu, gbA[b], off);
            gbB[b] += __shfl_xor_sync(0xffffffffu, gbB[b], off);
        }
    }
    {
        float bA = __ldg(&bias[colA]);
        float bB = __ldg(&bias[colB]);
#pragma unroll
        for (int b = 0; b < NB; ++b) { gbA[b] += bA; gbB[b] += bB; }
    }

    // ---- Wh slice -> registers (32 k x 2 cols as f32x2 pairs) ----
    unsigned long long wA[16], wB[16];
#pragma unroll
    for (int p = 0; p < 16; ++p) {
        int k = kq * 32 + 2 * p;
        wA[p] = pk2(__ldg(&Wh[k * 1024 + colA]), __ldg(&Wh[(k + 1) * 1024 + colA]));
        wB[p] = pk2(__ldg(&Wh[k * 1024 + colB]), __ldg(&Wh[(k + 1) * 1024 + colB]));
    }
    __syncthreads();
    // one-time: all CTAs' mbarriers armed + zeroed ht visible before any st.async
    asm volatile("barrier.cluster.arrive.aligned;" ::: "memory");
    asm volatile("barrier.cluster.wait.aligned;" ::: "memory");

    float ct[NB] = {0.f, 0.f, 0.f, 0.f};

    // ---- 64 periods x NB phases, no intra-loop __syncthreads ----
    for (int t = 0; t < 64; ++t) {
        const uint32_t rbuf = (uint32_t)(t & 1);
        const uint32_t wbuf = (uint32_t)((t + 1) & 1);
        const uint32_t wpar = (uint32_t)(((t - 1) >> 1) & 1);
#pragma unroll
        for (int b = 0; b < NB; ++b) {
            if (t > 0) {
                uint32_t ba = mbarb + (rbuf * NB + (uint32_t)b) * 8u;
                mbar_wait(ba, wpar);                       // every warp
                if (tid == 0) mbar_arrive_expect(ba, 1024); // re-arm t+2
            }

            // matvec for batch b over this lane's k-block (conflict-free)
            unsigned long long accA = 0ull, accB = 0ull;
            const uint32_t a = htb +
                (uint32_t)((((rbuf * NB + (uint32_t)b) * 8 + (uint32_t)kq) * BLKF) * 4);
#pragma unroll
            for (int q = 0; q < 8; ++q) {
                unsigned long long hA, hB;
                asm volatile("ld.shared.v2.u64 {%0, %1}, [%2];"
                             : "=l"(hA), "=l"(hB) : "r"(a + (uint32_t)(q * 16)));
                ffma2(accA, wA[2 * q],     hA);
                ffma2(accA, wA[2 * q + 1], hB);
                ffma2(accB, wB[2 * q],     hA);
                ffma2(accB, wB[2 * q + 1], hB);
            }
            float2 fA = upk2(accA), fB = upk2(accB);
            float pA = fA.x + fA.y;
            float pB = fB.x + fB.y;

            // all-reduce over the 8 kq lanes
#pragma unroll
            for (int off = 1; off < 8; off <<= 1) {
                pA += __shfl_xor_sync(0xffffffffu, pA, off);
                pB += __shfl_xor_sync(0xffffffffu, pB, off);
            }
            pA += gbA[b];
            pB += gbB[b];

            // exchange with opposite-cp lane -> every lane has all 4 gates
            float qA = __shfl_xor_sync(0xffffffffu, pA, 8);
            float qB = __shfl_xor_sync(0xffffffffu, pB, 8);
            float gi = cp ? qA : pA;
            float gf = cp ? qB : pB;
            float gg = cp ? pA : qA;
            float go = cp ? pB : qB;

            float c  = sig_mufu(gf) * ct[b] + sig_mufu(gi) * tanh_mufu(gg);
            ct[b] = c;
            float hv = sig_mufu(go) * tanh_mufu(c);

            // scatter: cp==0 lanes (32 hl x 8 kq) send h(b,hl) to rank kq
            // (own rank included -> all deliveries barrier-tracked)
            if (cp == 0) {
                uint32_t laddr = htb +
                    (uint32_t)(((((wbuf * NB + (uint32_t)b) * 8 + (uint32_t)r) * BLKF) + (uint32_t)hl) * 4);
                st_async_f32(laddr, mbarb + (wbuf * NB + (uint32_t)b) * 8u, hv, kq);
            }
        }
    }

    // ---- final waits: ht(64) of each batch lands in buf 0, parity 1 ----
#pragma unroll
    for (int b = 0; b < NB; ++b)
        mbar_wait(mbarb + (uint32_t)(b * 8), 1);
    __syncthreads();

    // ---- epilogue: out[cbase+b] = ht_b @ Wf + bf (rank 0 only) ----
    if (r == 0) {
        int b  = tid >> 7;            // 0..3 (128 threads per batch)
        int kk = (tid & 127) * 2;
        float v = htbuf[0][b][kk >> 5][kk & 31] * Wf[kk]
                + htbuf[0][b][(kk + 1) >> 5][(kk + 1) & 31] * Wf[kk + 1];
#pragma unroll
        for (int off = 16; off > 0; off >>= 1) v += __shfl_xor_sync(0xffffffffu, v, off);
        if (lane == 0) red_s[wrp] = v;
        __syncthreads();
        if ((tid & 127) == 0) {
            float o = bf[0];
#pragma unroll
            for (int w = 0; w < 4; ++w) o += red_s[(tid >> 7) * 4 + w];
            out[cbase + (tid >> 7)] = o;
        }
    }
    // keep the cluster alive until everyone is done with peers' smem
    asm volatile("barrier.cluster.arrive.aligned;" ::: "memory");
    asm volatile("barrier.cluster.wait.aligned;" ::: "memory");
}

// ============================================================================
extern "C" void kernel_launch(void* const* d_in, const int* in_sizes, int n_in,
                              void* d_out, int out_size) {
    (void)in_sizes; (void)n_in; (void)out_size;
    const float* x    = (const float*)d_in[0];
    const float* Wa   = (const float*)d_in[1];
    // d_in[2] = ba : constant across seq, cancels inside softmax — unused
    const float* Wi   = (const float*)d_in[3];
    const float* Wh   = (const float*)d_in[4];
    const float* bias = (const float*)d_in[5];
    const float* Wf   = (const float*)d_in[6];
    const float* bf   = (const float*)d_in[7];
    float* out = (float*)d_out;

    k_context<<<128, 256>>>(x, Wa);
    k_recur<<<64, 512>>>(Wi, Wh, bias, Wf, bf, out);
}